// round 1
// baseline (speedup 1.0000x reference)
#include <cuda_runtime.h>
#include <cuda_bf16.h>
#include <math.h>

#define N_NODES  100000
#define D        128
#define D_FF     256
#define N_CLASSES 26
#define N_GRAPHS 512

// ---------------- scratch (static __device__ — allocation-guard safe) -------
__device__ float g_h  [(size_t)N_NODES * D];
__device__ float g_agg[(size_t)N_NODES * D];
__device__ float g_act[(size_t)N_NODES * D];
__device__ int   g_deg [N_NODES];
__device__ float g_dinv[N_NODES];
__device__ float g_psum[N_GRAPHS * D];
__device__ int   g_cnt [N_GRAPHS];
__device__ int   g_is64;

// ---------------- helpers ---------------------------------------------------
__device__ __forceinline__ long long load_index(const void* p, long long pos, int is64) {
    if (is64) return ((const long long*)p)[pos];
    return (long long)((const int*)p)[pos];
}

__device__ __forceinline__ void red_add_v4(float* addr, float4 v) {
    asm volatile("red.global.add.v4.f32 [%0], {%1, %2, %3, %4};"
                 :: "l"(addr), "f"(v.x), "f"(v.y), "f"(v.z), "f"(v.w)
                 : "memory");
}

// ---------------- kernels ---------------------------------------------------
__global__ void detect_kernel(const int* ei) {
    if (blockIdx.x == 0 && threadIdx.x == 0) {
        int all0 = 1;
        #pragma unroll
        for (int i = 1; i < 64; i += 2) all0 &= (ei[i] == 0);
        g_is64 = all0;
    }
}

__global__ void init_kernel(int n) {
    int i = blockIdx.x * blockDim.x + threadIdx.x;
    if (i < n) g_deg[i] = 1;
    if (i < N_GRAPHS * D) g_psum[i] = 0.f;
    if (i < N_GRAPHS) g_cnt[i] = 0;
}

__global__ void degree_kernel(const void* ei, int E) {
    int is64 = g_is64;
    for (long long e = blockIdx.x * (long long)blockDim.x + threadIdx.x;
         e < E; e += (long long)gridDim.x * blockDim.x) {
        long long d = load_index(ei, (long long)E + e, is64);
        atomicAdd(&g_deg[d], 1);
    }
}

__global__ void dinv_kernel(int n) {
    int i = blockIdx.x * blockDim.x + threadIdx.x;
    if (i < n) g_dinv[i] = rsqrtf((float)g_deg[i]);
}

// H = X@W, AGG = H * dinv^2.  use_x: layer-0 reads external x, else g_act.
__global__ void gcn_gemm_kernel(const float* __restrict__ Xext,
                                const float* __restrict__ W,
                                int n, int use_x) {
    extern __shared__ float smem[];
    float* Ws = smem;                 // 128*128
    float* Xs = smem + 128 * 128;     // 64*132
    const int XS_LD = 132;
    const float* X = use_x ? Xext : g_act;

    int row0 = blockIdx.x * 64;

    for (int i = threadIdx.x; i < 128 * 128 / 4; i += 256)
        ((float4*)Ws)[i] = ((const float4*)W)[i];

    int rows = n - row0; if (rows > 64) rows = 64;
    for (int i = threadIdx.x; i < rows * 32; i += 256) {
        int r = i >> 5, c4 = i & 31;
        ((float4*)(Xs + r * XS_LD))[c4] =
            ((const float4*)(X + (size_t)(row0 + r) * D))[c4];
    }
    __syncthreads();

    int ty = threadIdx.x >> 4;
    int tx = threadIdx.x & 15;

    float acc[4][8];
    #pragma unroll
    for (int i = 0; i < 4; i++)
        #pragma unroll
        for (int j = 0; j < 8; j++) acc[i][j] = 0.f;

    #pragma unroll 4
    for (int k = 0; k < 128; ++k) {
        const float* wrow = &Ws[k * 128 + tx * 8];
        float4 w0 = *(const float4*)(wrow);
        float4 w1 = *(const float4*)(wrow + 4);
        float wv[8] = {w0.x, w0.y, w0.z, w0.w, w1.x, w1.y, w1.z, w1.w};
        float a[4];
        #pragma unroll
        for (int i = 0; i < 4; i++) a[i] = Xs[(ty * 4 + i) * XS_LD + k];
        #pragma unroll
        for (int i = 0; i < 4; i++)
            #pragma unroll
            for (int j = 0; j < 8; j++) acc[i][j] = fmaf(a[i], wv[j], acc[i][j]);
    }

    #pragma unroll
    for (int i = 0; i < 4; i++) {
        int r = row0 + ty * 4 + i;
        if (r < n) {
            float dv = g_dinv[r];
            float d2 = dv * dv;
            size_t base = (size_t)r * D + tx * 8;
            float4 h0 = make_float4(acc[i][0], acc[i][1], acc[i][2], acc[i][3]);
            float4 h1 = make_float4(acc[i][4], acc[i][5], acc[i][6], acc[i][7]);
            *(float4*)(g_h + base)     = h0;
            *(float4*)(g_h + base + 4) = h1;
            *(float4*)(g_agg + base)     = make_float4(h0.x*d2, h0.y*d2, h0.z*d2, h0.w*d2);
            *(float4*)(g_agg + base + 4) = make_float4(h1.x*d2, h1.y*d2, h1.z*d2, h1.w*d2);
        }
    }
}

__global__ void edge_kernel(const void* ei, int E) {
    int is64 = g_is64;
    int lane = threadIdx.x & 31;
    long long warp = (blockIdx.x * (long long)blockDim.x + threadIdx.x) >> 5;
    long long nwarps = ((long long)gridDim.x * blockDim.x) >> 5;
    for (long long e = warp; e < E; e += nwarps) {
        long long s = load_index(ei, e, is64);
        long long d = load_index(ei, (long long)E + e, is64);
        float w = g_dinv[s] * g_dinv[d];
        float4 v = *(const float4*)(g_h + (size_t)s * D + lane * 4);
        v.x *= w; v.y *= w; v.z *= w; v.w *= w;
        red_add_v4(g_agg + (size_t)d * D + lane * 4, v);
    }
}

__global__ void bias_relu_kernel(const float* __restrict__ b, int n) {
    long long i = blockIdx.x * (long long)blockDim.x + threadIdx.x;
    long long total = (long long)n * 32;
    if (i < total) {
        int c4 = (int)(i & 31);
        float4 bb = ((const float4*)b)[c4];
        float4 a = ((const float4*)g_agg)[i];
        a.x = fmaxf(a.x + bb.x, 0.f);
        a.y = fmaxf(a.y + bb.y, 0.f);
        a.z = fmaxf(a.z + bb.z, 0.f);
        a.w = fmaxf(a.w + bb.w, 0.f);
        ((float4*)g_act)[i] = a;
    }
}

__global__ void pool_kernel(const void* batch, int n) {
    int is64 = g_is64;
    int lane = threadIdx.x & 31;
    long long warp = (blockIdx.x * (long long)blockDim.x + threadIdx.x) >> 5;
    long long nwarps = ((long long)gridDim.x * blockDim.x) >> 5;
    for (long long nd = warp; nd < n; nd += nwarps) {
        long long g = load_index(batch, nd, is64);
        float4 v = *(const float4*)(g_act + (size_t)nd * D + lane * 4);
        red_add_v4(g_psum + (size_t)g * D + lane * 4, v);
        if (lane == 0) atomicAdd(&g_cnt[g], 1);
    }
}

__global__ void fc_kernel(const float* __restrict__ Wfc, const float* __restrict__ bfc,
                          const float* __restrict__ Wfc2, const float* __restrict__ bfc2,
                          float* __restrict__ out) {
    __shared__ float p[D];
    __shared__ float h1[D_FF];
    int g = blockIdx.x;
    int t = threadIdx.x;

    int c = g_cnt[g]; if (c < 1) c = 1;
    float inv = 1.f / (float)c;
    if (t < D) p[t] = g_psum[g * D + t] * inv;
    __syncthreads();

    float s = bfc[t];
    #pragma unroll 4
    for (int k = 0; k < D; k++) s = fmaf(p[k], Wfc[k * D_FF + t], s);
    h1[t] = fmaxf(s, 0.f);
    __syncthreads();

    if (t < N_CLASSES) {
        float s2 = bfc2[t];
        #pragma unroll 4
        for (int k = 0; k < D_FF; k++) s2 = fmaf(h1[k], Wfc2[k * N_CLASSES + t], s2);
        out[g * N_CLASSES + t] = s2;
    }
}

// ---------------- launch -----------------------------------------------------
extern "C" void kernel_launch(void* const* d_in, const int* in_sizes, int n_in,
                              void* d_out, int out_size) {
    const float* x    = (const float*)d_in[0];
    const void*  ei   = d_in[1];
    const void*  batch= d_in[2];
    const float* W1   = (const float*)d_in[3];
    const float* b1   = (const float*)d_in[4];
    const float* W2   = (const float*)d_in[5];
    const float* b2   = (const float*)d_in[6];
    const float* W3   = (const float*)d_in[7];
    const float* b3   = (const float*)d_in[8];
    const float* Wfc  = (const float*)d_in[9];
    const float* bfc  = (const float*)d_in[10];
    const float* Wfc2 = (const float*)d_in[11];
    const float* bfc2 = (const float*)d_in[12];
    float* out = (float*)d_out;

    int n = in_sizes[0] / D;
    int E = in_sizes[1] / 2;

    static bool attr_set = false;
    const int GEMM_SMEM = (128 * 128 + 64 * 132) * 4;
    if (!attr_set) {
        cudaFuncSetAttribute(gcn_gemm_kernel,
                             cudaFuncAttributeMaxDynamicSharedMemorySize, GEMM_SMEM);
        attr_set = true;
    }

    detect_kernel<<<1, 32>>>((const int*)ei);
    init_kernel<<<(n + 255) / 256, 256>>>(n);
    degree_kernel<<<(E + 255) / 256, 256>>>(ei, E);
    dinv_kernel<<<(n + 255) / 256, 256>>>(n);

    int gemm_blocks = (n + 63) / 64;
    long long elem4 = (long long)n * 32;
    int br_blocks = (int)((elem4 + 255) / 256);
    int edge_blocks = 4096;

    const float* Ws_[3] = {W1, W2, W3};
    const float* bs_[3] = {b1, b2, b3};
    for (int l = 0; l < 3; l++) {
        gcn_gemm_kernel<<<gemm_blocks, 256, GEMM_SMEM>>>(x, Ws_[l], n, l == 0 ? 1 : 0);
        edge_kernel<<<edge_blocks, 256>>>(ei, E);
        bias_relu_kernel<<<br_blocks, 256>>>(bs_[l], n);
    }

    pool_kernel<<<(n * 32 + 255) / 256, 256>>>(batch, n);
    fc_kernel<<<N_GRAPHS, D_FF>>>(Wfc, bfc, Wfc2, bfc2, out);
}

// round 2
// speedup vs baseline: 1.8781x; 1.8781x over previous
#include <cuda_runtime.h>
#include <cuda_bf16.h>
#include <math.h>

#define N_NODES   100000
#define MAX_E     3300000
#define D         128
#define D_FF      256
#define N_CLASSES 26
#define N_GRAPHS  512
#define SCAN_BLK  1024

// ---------------- scratch (static __device__ — allocation-guard safe) -------
__device__ float g_h   [(size_t)N_NODES * D];
__device__ float g_act [(size_t)N_NODES * D];
__device__ int   g_edeg[N_NODES];          // edge-only in-degree
__device__ float g_dinv[N_NODES];
__device__ int   g_off [N_NODES + 1];      // CSR row offsets (by dst)
__device__ int   g_fill[N_NODES];          // running fill pointers
__device__ int   g_bsum[256];              // scan block sums
__device__ int   g_csr_src[MAX_E];
__device__ float g_csr_w  [MAX_E];
__device__ int   g_batch[N_NODES];
__device__ float g_psum[N_GRAPHS * D];
__device__ int   g_cnt [N_GRAPHS];
__device__ int   g_is64;

// ---------------- helpers ---------------------------------------------------
__device__ __forceinline__ long long load_index(const void* p, long long pos, int is64) {
    if (is64) return ((const long long*)p)[pos];
    return (long long)((const int*)p)[pos];
}

__device__ __forceinline__ void red_add_v4(float* addr, float4 v) {
    asm volatile("red.global.add.v4.f32 [%0], {%1, %2, %3, %4};"
                 :: "l"(addr), "f"(v.x), "f"(v.y), "f"(v.z), "f"(v.w)
                 : "memory");
}

// ---------------- setup kernels ---------------------------------------------
__global__ void detect_kernel(const int* ei) {
    if (blockIdx.x == 0 && threadIdx.x == 0) {
        int all0 = 1;
        #pragma unroll
        for (int i = 1; i < 64; i += 2) all0 &= (ei[i] == 0);
        g_is64 = all0;
    }
}

__global__ void init_kernel(int n) {
    int i = blockIdx.x * blockDim.x + threadIdx.x;
    if (i < n) g_edeg[i] = 0;
    if (i < N_GRAPHS * D) g_psum[i] = 0.f;
    if (i < N_GRAPHS) g_cnt[i] = 0;
}

__global__ void degree_kernel(const void* ei, int E) {
    int is64 = g_is64;
    for (long long e = blockIdx.x * (long long)blockDim.x + threadIdx.x;
         e < E; e += (long long)gridDim.x * blockDim.x) {
        long long d = load_index(ei, (long long)E + e, is64);
        atomicAdd(&g_edeg[d], 1);
    }
}

__global__ void dinv_kernel(int n) {
    int i = blockIdx.x * blockDim.x + threadIdx.x;
    if (i < n) g_dinv[i] = rsqrtf((float)(g_edeg[i] + 1));   // +1 self loop
}

// exclusive scan, phase A: per-block (1024 elems) scan + block total
__global__ void scanA_kernel(int n) {
    __shared__ int ssum[256];
    int b = blockIdx.x, t = threadIdx.x;
    int base = b * SCAN_BLK + t * 4;
    int v[4];
    #pragma unroll
    for (int j = 0; j < 4; j++) {
        int idx = base + j;
        v[j] = (idx < n) ? g_edeg[idx] : 0;
    }
    int tot = v[0] + v[1] + v[2] + v[3];
    ssum[t] = tot;
    __syncthreads();
    // Hillis-Steele inclusive scan over 256 thread totals
    #pragma unroll
    for (int ofs = 1; ofs < 256; ofs <<= 1) {
        int val = (t >= ofs) ? ssum[t - ofs] : 0;
        __syncthreads();
        ssum[t] += val;
        __syncthreads();
    }
    int excl = ssum[t] - tot;   // exclusive prefix for this thread
    int run = excl;
    #pragma unroll
    for (int j = 0; j < 4; j++) {
        int idx = base + j;
        if (idx < n) g_off[idx] = run;
        run += v[j];
    }
    if (t == 255) g_bsum[b] = ssum[255];
}

// phase B: scan block sums (single thread; nb <= 128)
__global__ void scanB_kernel(int nb, int n) {
    if (threadIdx.x == 0 && blockIdx.x == 0) {
        int run = 0;
        for (int b = 0; b < nb; b++) {
            int t = g_bsum[b];
            g_bsum[b] = run;
            run += t;
        }
        g_off[n] = run;   // == E
    }
}

// phase C: add block offsets; init fill pointers
__global__ void scanC_kernel(int n) {
    int i = blockIdx.x * blockDim.x + threadIdx.x;
    if (i < n) {
        int o = g_off[i] + g_bsum[i / SCAN_BLK];
        g_off[i] = o;
        g_fill[i] = o;
    }
}

// scatter edges into CSR (by dst), with precomputed weight
__global__ void fill_kernel(const void* ei, int E) {
    int is64 = g_is64;
    for (long long e = blockIdx.x * (long long)blockDim.x + threadIdx.x;
         e < E; e += (long long)gridDim.x * blockDim.x) {
        long long s = load_index(ei, e, is64);
        long long d = load_index(ei, (long long)E + e, is64);
        int pos = atomicAdd(&g_fill[d], 1);
        g_csr_src[pos] = (int)s;
        g_csr_w[pos] = g_dinv[s] * g_dinv[d];
    }
}

// batch -> int32 + per-graph node counts
__global__ void batch_kernel(const void* batch, int n) {
    int is64 = g_is64;
    int i = blockIdx.x * blockDim.x + threadIdx.x;
    if (i < n) {
        int g = (int)load_index(batch, i, is64);
        g_batch[i] = g;
        atomicAdd(&g_cnt[g], 1);
    }
}

// ---------------- per-layer kernels -----------------------------------------
// H = X@W  (only h; agg handled in gather). use_x: layer 0 reads external x.
__global__ void gcn_gemm_kernel(const float* __restrict__ Xext,
                                const float* __restrict__ W,
                                int n, int use_x) {
    extern __shared__ float smem[];
    float* Ws = smem;                 // 128*128
    float* Xs = smem + 128 * 128;     // 64*132
    const int XS_LD = 132;
    const float* X = use_x ? Xext : g_act;

    int row0 = blockIdx.x * 64;

    for (int i = threadIdx.x; i < 128 * 128 / 4; i += 256)
        ((float4*)Ws)[i] = ((const float4*)W)[i];

    int rows = n - row0; if (rows > 64) rows = 64;
    for (int i = threadIdx.x; i < rows * 32; i += 256) {
        int r = i >> 5, c4 = i & 31;
        ((float4*)(Xs + r * XS_LD))[c4] =
            ((const float4*)(X + (size_t)(row0 + r) * D))[c4];
    }
    __syncthreads();

    int ty = threadIdx.x >> 4;
    int tx = threadIdx.x & 15;

    float acc[4][8];
    #pragma unroll
    for (int i = 0; i < 4; i++)
        #pragma unroll
        for (int j = 0; j < 8; j++) acc[i][j] = 0.f;

    #pragma unroll 4
    for (int k = 0; k < 128; ++k) {
        const float* wrow = &Ws[k * 128 + tx * 8];
        float4 w0 = *(const float4*)(wrow);
        float4 w1 = *(const float4*)(wrow + 4);
        float wv[8] = {w0.x, w0.y, w0.z, w0.w, w1.x, w1.y, w1.z, w1.w};
        float a[4];
        #pragma unroll
        for (int i = 0; i < 4; i++) a[i] = Xs[(ty * 4 + i) * XS_LD + k];
        #pragma unroll
        for (int i = 0; i < 4; i++)
            #pragma unroll
            for (int j = 0; j < 8; j++) acc[i][j] = fmaf(a[i], wv[j], acc[i][j]);
    }

    #pragma unroll
    for (int i = 0; i < 4; i++) {
        int r = row0 + ty * 4 + i;
        if (r < n) {
            size_t base = (size_t)r * D + tx * 8;
            *(float4*)(g_h + base)     = make_float4(acc[i][0], acc[i][1], acc[i][2], acc[i][3]);
            *(float4*)(g_h + base + 4) = make_float4(acc[i][4], acc[i][5], acc[i][6], acc[i][7]);
        }
    }
}

// warp-per-node gather: acc = d2*h[nd] + sum_e w_e * h[src_e]; relu(acc + b)
// do_pool: scatter into pooled sums instead of storing act.
__global__ void gather_kernel(const float* __restrict__ bias, int n, int do_pool) {
    int gwarp = (blockIdx.x * blockDim.x + threadIdx.x) >> 5;
    if (gwarp >= n) return;
    int lane = threadIdx.x & 31;
    int nd = gwarp;

    const float4* hp = (const float4*)g_h;
    float dv = g_dinv[nd];
    float d2 = dv * dv;
    float4 acc = hp[(size_t)nd * 32 + lane];
    acc.x *= d2; acc.y *= d2; acc.z *= d2; acc.w *= d2;

    int beg = g_off[nd];
    int end = g_off[nd + 1];
    for (int e = beg; e < end; e++) {
        int s = __ldg(&g_csr_src[e]);
        float w = __ldg(&g_csr_w[e]);
        float4 v = hp[(size_t)s * 32 + lane];
        acc.x = fmaf(w, v.x, acc.x);
        acc.y = fmaf(w, v.y, acc.y);
        acc.z = fmaf(w, v.z, acc.z);
        acc.w = fmaf(w, v.w, acc.w);
    }

    float4 bb = ((const float4*)bias)[lane];
    acc.x = fmaxf(acc.x + bb.x, 0.f);
    acc.y = fmaxf(acc.y + bb.y, 0.f);
    acc.z = fmaxf(acc.z + bb.z, 0.f);
    acc.w = fmaxf(acc.w + bb.w, 0.f);

    if (do_pool) {
        int g = g_batch[nd];
        red_add_v4(g_psum + (size_t)g * D + lane * 4, acc);
    } else {
        ((float4*)g_act)[(size_t)nd * 32 + lane] = acc;
    }
}

// fused MLP head
__global__ void fc_kernel(const float* __restrict__ Wfc, const float* __restrict__ bfc,
                          const float* __restrict__ Wfc2, const float* __restrict__ bfc2,
                          float* __restrict__ out) {
    __shared__ float p[D];
    __shared__ float h1[D_FF];
    int g = blockIdx.x;
    int t = threadIdx.x;

    int c = g_cnt[g]; if (c < 1) c = 1;
    float inv = 1.f / (float)c;
    if (t < D) p[t] = g_psum[g * D + t] * inv;
    __syncthreads();

    float s = bfc[t];
    #pragma unroll 4
    for (int k = 0; k < D; k++) s = fmaf(p[k], Wfc[k * D_FF + t], s);
    h1[t] = fmaxf(s, 0.f);
    __syncthreads();

    if (t < N_CLASSES) {
        float s2 = bfc2[t];
        #pragma unroll 4
        for (int k = 0; k < D_FF; k++) s2 = fmaf(h1[k], Wfc2[k * N_CLASSES + t], s2);
        out[g * N_CLASSES + t] = s2;
    }
}

// ---------------- launch -----------------------------------------------------
extern "C" void kernel_launch(void* const* d_in, const int* in_sizes, int n_in,
                              void* d_out, int out_size) {
    const float* x    = (const float*)d_in[0];
    const void*  ei   = d_in[1];
    const void*  batch= d_in[2];
    const float* W1   = (const float*)d_in[3];
    const float* b1   = (const float*)d_in[4];
    const float* W2   = (const float*)d_in[5];
    const float* b2   = (const float*)d_in[6];
    const float* W3   = (const float*)d_in[7];
    const float* b3   = (const float*)d_in[8];
    const float* Wfc  = (const float*)d_in[9];
    const float* bfc  = (const float*)d_in[10];
    const float* Wfc2 = (const float*)d_in[11];
    const float* bfc2 = (const float*)d_in[12];
    float* out = (float*)d_out;

    int n = in_sizes[0] / D;
    int E = in_sizes[1] / 2;

    static bool attr_set = false;
    const int GEMM_SMEM = (128 * 128 + 64 * 132) * 4;
    if (!attr_set) {
        cudaFuncSetAttribute(gcn_gemm_kernel,
                             cudaFuncAttributeMaxDynamicSharedMemorySize, GEMM_SMEM);
        attr_set = true;
    }

    // ---- one-time setup: normalization + CSR + batch ----
    detect_kernel<<<1, 32>>>((const int*)ei);
    init_kernel<<<(n + 255) / 256, 256>>>(n);
    degree_kernel<<<2048, 256>>>(ei, E);
    dinv_kernel<<<(n + 255) / 256, 256>>>(n);
    int nb = (n + SCAN_BLK - 1) / SCAN_BLK;
    scanA_kernel<<<nb, 256>>>(n);
    scanB_kernel<<<1, 32>>>(nb, n);
    scanC_kernel<<<(n + 255) / 256, 256>>>(n);
    fill_kernel<<<2048, 256>>>(ei, E);
    batch_kernel<<<(n + 255) / 256, 256>>>(batch, n);

    // ---- layers ----
    int gemm_blocks = (n + 63) / 64;
    int gather_blocks = (n * 32 + 255) / 256;

    gcn_gemm_kernel<<<gemm_blocks, 256, GEMM_SMEM>>>(x, W1, n, 1);
    gather_kernel<<<gather_blocks, 256>>>(b1, n, 0);

    gcn_gemm_kernel<<<gemm_blocks, 256, GEMM_SMEM>>>(x, W2, n, 0);
    gather_kernel<<<gather_blocks, 256>>>(b2, n, 0);

    gcn_gemm_kernel<<<gemm_blocks, 256, GEMM_SMEM>>>(x, W3, n, 0);
    gather_kernel<<<gather_blocks, 256>>>(b3, n, 1);   // fused pool

    fc_kernel<<<N_GRAPHS, D_FF>>>(Wfc, bfc, Wfc2, bfc2, out);
}